// round 4
// baseline (speedup 1.0000x reference)
#include <cuda_runtime.h>
#include <cstdint>

#define NN 50000     // nodes
#define HD 64        // hidden = out
#define RR 50        // relations
#define EE 800000    // edges
#define NB 4         // blocks (block-diagonal)
#define DB 16        // block dim

// ---------------- scratch (device globals; no allocation allowed) ----------------
__device__ int   g_cnt[NN * RR];      // per (dst,rel) edge counts
__device__ int   g_hist[RR];          // relation histogram
__device__ int   g_cursor[RR];        // scatter cursors (exclusive prefix)
__device__ int4  g_ep[EE];            // sorted edges: {src, dst, rel, scale_bits}
__device__ float g_h0[NN * HD];
__device__ float g_h1[NN * HD];

typedef unsigned long long u64;

// Resolve intermediate buffers on the DEVICE side (no cudaGetSymbolAddress on host,
// keeping kernel_launch a pure sequence of kernel launches for graph capture).
__device__ __forceinline__ float* pick_buf(int which, float* io) {
    return which == 0 ? g_h0 : (which == 1 ? g_h1 : io);
}
__device__ __forceinline__ const float* pick_cbuf(int which, const float* io) {
    return which == 0 ? g_h0 : (which == 1 ? g_h1 : io);
}

__device__ __forceinline__ u64 f2pack(float a, float b) {
    u64 r; asm("mov.b64 %0,{%1,%2};" : "=l"(r) : "f"(a), "f"(b)); return r;
}
__device__ __forceinline__ u64 f2dup(float a) {
    u64 r; asm("mov.b64 %0,{%1,%1};" : "=l"(r) : "f"(a)); return r;
}
__device__ __forceinline__ u64 f2fma(u64 a, u64 b, u64 c) {
    u64 d; asm("fma.rn.f32x2 %0,%1,%2,%3;" : "=l"(d) : "l"(a), "l"(b), "l"(c)); return d;
}
__device__ __forceinline__ u64 f2mul(u64 a, u64 b) {
    u64 d; asm("mul.rn.f32x2 %0,%1,%2;" : "=l"(d) : "l"(a), "l"(b)); return d;
}
__device__ __forceinline__ void f2unpack(u64 v, float& a, float& b) {
    asm("mov.b64 {%0,%1},%2;" : "=f"(a), "=f"(b) : "l"(v));
}
__device__ __forceinline__ void red2(float* p, float a, float b) {
    asm volatile("red.global.add.v2.f32 [%0],{%1,%2};" :: "l"(p), "f"(a), "f"(b) : "memory");
}

// ---------------- setup kernels ----------------
__global__ void k_zero() {
    int i = blockIdx.x * blockDim.x + threadIdx.x;
    int stride = gridDim.x * blockDim.x;
    for (int j = i; j < NN * RR; j += stride) g_cnt[j] = 0;
    if (i < RR) g_hist[i] = 0;
}

__global__ void k_count(const int* __restrict__ dst, const int* __restrict__ et) {
    __shared__ int sh[RR];
    for (int i = threadIdx.x; i < RR; i += blockDim.x) sh[i] = 0;
    __syncthreads();
    int i = blockIdx.x * blockDim.x + threadIdx.x;
    int stride = gridDim.x * blockDim.x;
    for (; i < EE; i += stride) {
        int d = dst[i], r = et[i];
        atomicAdd(&g_cnt[d * RR + r], 1);
        atomicAdd(&sh[r], 1);
    }
    __syncthreads();
    for (int i = threadIdx.x; i < RR; i += blockDim.x) atomicAdd(&g_hist[i], sh[i]);
}

__global__ void k_scan() {
    // single thread: 50 values
    int off = 0;
    for (int r = 0; r < RR; r++) { g_cursor[r] = off; off += g_hist[r]; }
}

__global__ void k_scatter(const int* __restrict__ src, const int* __restrict__ dst,
                          const int* __restrict__ et) {
    int i = blockIdx.x * blockDim.x + threadIdx.x;
    int stride = gridDim.x * blockDim.x;
    for (; i < EE; i += stride) {
        int s = src[i], d = dst[i], r = et[i];
        int p = atomicAdd(&g_cursor[r], 1);
        int c = g_cnt[d * RR + r];
        float sc = 1.0f / (float)(c > 1 ? c : 1);
        g_ep[p] = make_int4(s, d, r, __float_as_int(sc));
    }
}

// ---------------- root GEMM: out[n,:] = x[n,:] @ W(64x64) + bias ----------------
__global__ void __launch_bounds__(256) k_root(const float* __restrict__ xio, int wx,
                                              const float* __restrict__ w,
                                              const float* __restrict__ bias,
                                              float* __restrict__ oio, int wo) {
    const float* x = pick_cbuf(wx, xio);
    float* out = pick_buf(wo, oio);
    int gw = (blockIdx.x * blockDim.x + threadIdx.x) >> 5;
    int lane = threadIdx.x & 31;
    int nwarps = (gridDim.x * blockDim.x) >> 5;

    u64 wreg[64];
#pragma unroll
    for (int d = 0; d < 64; d++) {
        float2 wv = *(const float2*)(w + (size_t)d * 64 + 2 * lane);
        wreg[d] = f2pack(wv.x, wv.y);
    }
    float2 bv = *(const float2*)(bias + 2 * lane);
    u64 b2 = f2pack(bv.x, bv.y);

    for (int n = gw; n < NN; n += nwarps) {
        const float4* xr = (const float4*)(x + (size_t)n * 64);
        u64 acc = b2;
#pragma unroll
        for (int t = 0; t < 16; t++) {
            float4 q = xr[t];
            acc = f2fma(wreg[4 * t + 0], f2dup(q.x), acc);
            acc = f2fma(wreg[4 * t + 1], f2dup(q.y), acc);
            acc = f2fma(wreg[4 * t + 2], f2dup(q.z), acc);
            acc = f2fma(wreg[4 * t + 3], f2dup(q.w), acc);
        }
        float a, b; f2unpack(acc, a, b);
        *(float2*)(out + (size_t)n * 64 + 2 * lane) = make_float2(a, b);
    }
}

// ---------------- edge transform + scatter, block-diagonal W [R,4,16,16] ----------------
__global__ void __launch_bounds__(256) k_edge_bd(const float* __restrict__ xio, int wx,
                                                 const float* __restrict__ wrel,
                                                 float* __restrict__ oio, int wo, int chunk) {
    const float* x = pick_cbuf(wx, xio);
    float* out = pick_buf(wo, oio);
    int gw = (blockIdx.x * blockDim.x + threadIdx.x) >> 5;
    int lane = threadIdx.x & 31;
    long e0 = (long)gw * chunk;
    if (e0 >= EE) return;
    int e1 = (int)e0 + chunk; if (e1 > EE) e1 = EE;

    int b = lane >> 3;             // block 0..3 (outputs 2l,2l+1 live in block b)
    int col = (2 * lane) & 15;     // column within block
    u64 wreg[16];
    int prev = -1;

    for (int e = (int)e0; e < e1; e++) {
        int4 ep = g_ep[e];
        int r = ep.z;
        if (r != prev) {
            prev = r;
            const float* wb = wrel + ((size_t)r * NB + b) * 256 + col;
#pragma unroll
            for (int d = 0; d < 16; d++) {
                float2 wv = *(const float2*)(wb + d * 16);
                wreg[d] = f2pack(wv.x, wv.y);
            }
        }
        const float4* xr = (const float4*)(x + (size_t)ep.x * 64) + b * 4;
        u64 acc = 0ull;
#pragma unroll
        for (int t = 0; t < 4; t++) {
            float4 q = xr[t];
            acc = f2fma(wreg[4 * t + 0], f2dup(q.x), acc);
            acc = f2fma(wreg[4 * t + 1], f2dup(q.y), acc);
            acc = f2fma(wreg[4 * t + 2], f2dup(q.z), acc);
            acc = f2fma(wreg[4 * t + 3], f2dup(q.w), acc);
        }
        acc = f2mul(acc, f2dup(__int_as_float(ep.w)));
        float a, bb; f2unpack(acc, a, bb);
        red2(out + (size_t)ep.y * 64 + 2 * lane, a, bb);
    }
}

// ---------------- edge transform + scatter, full W [R,64,64] ----------------
__global__ void __launch_bounds__(256) k_edge_full(const float* __restrict__ xio, int wx,
                                                   const float* __restrict__ wrel,
                                                   float* __restrict__ oio, int wo, int chunk) {
    const float* x = pick_cbuf(wx, xio);
    float* out = pick_buf(wo, oio);
    int gw = (blockIdx.x * blockDim.x + threadIdx.x) >> 5;
    int lane = threadIdx.x & 31;
    long e0 = (long)gw * chunk;
    if (e0 >= EE) return;
    int e1 = (int)e0 + chunk; if (e1 > EE) e1 = EE;

    u64 wreg[64];
    int prev = -1;

    for (int e = (int)e0; e < e1; e++) {
        int4 ep = g_ep[e];
        int r = ep.z;
        if (r != prev) {
            prev = r;
            const float* wb = wrel + (size_t)r * 4096 + 2 * lane;
#pragma unroll
            for (int d = 0; d < 64; d++) {
                float2 wv = *(const float2*)(wb + (size_t)d * 64);
                wreg[d] = f2pack(wv.x, wv.y);
            }
        }
        const float4* xr = (const float4*)(x + (size_t)ep.x * 64);
        u64 acc = 0ull;
#pragma unroll
        for (int t = 0; t < 16; t++) {
            float4 q = xr[t];
            acc = f2fma(wreg[4 * t + 0], f2dup(q.x), acc);
            acc = f2fma(wreg[4 * t + 1], f2dup(q.y), acc);
            acc = f2fma(wreg[4 * t + 2], f2dup(q.z), acc);
            acc = f2fma(wreg[4 * t + 3], f2dup(q.w), acc);
        }
        acc = f2mul(acc, f2dup(__int_as_float(ep.w)));
        float a, bb; f2unpack(acc, a, bb);
        red2(out + (size_t)ep.y * 64 + 2 * lane, a, bb);
    }
}

__global__ void k_relu(int which) {
    float* h = pick_buf(which, nullptr);
    int i = blockIdx.x * blockDim.x + threadIdx.x;
    int stride = gridDim.x * blockDim.x;
    float4* p = (float4*)h;
    for (; i < NN * HD / 4; i += stride) {
        float4 v = p[i];
        v.x = fmaxf(v.x, 0.f); v.y = fmaxf(v.y, 0.f);
        v.z = fmaxf(v.z, 0.f); v.w = fmaxf(v.w, 0.f);
        p[i] = v;
    }
}

// ---------------- host ----------------
extern "C" void kernel_launch(void* const* d_in, const int* in_sizes, int n_in,
                              void* d_out, int out_size) {
    const float* x       = (const float*)d_in[0];
    const int*   eidx    = (const int*)d_in[1];
    const int*   src     = eidx;
    const int*   dst     = eidx + EE;
    const int*   et      = (const int*)d_in[2];
    const float* w0_rel  = (const float*)d_in[3];
    const float* w0_root = (const float*)d_in[4];
    const float* b0      = (const float*)d_in[5];
    const float* w1_rel  = (const float*)d_in[6];
    const float* w1_root = (const float*)d_in[7];
    const float* b1      = (const float*)d_in[8];
    const float* w2_rel  = (const float*)d_in[9];
    const float* w2_root = (const float*)d_in[10];
    const float* b2      = (const float*)d_in[11];
    float* out = (float*)d_out;

    // setup: counts + relation-sort (counting sort by relation)
    k_zero<<<2560, 1024>>>();
    k_count<<<800, 1024>>>(dst, et);
    k_scan<<<1, 1>>>();
    k_scatter<<<800, 1024>>>(src, dst, et);

    // edge-kernel geometry: contiguous chunk per warp over relation-sorted edges
    const int EBLOCKS = 1184;                 // 8 warps/block
    const int TW = EBLOCKS * 8;
    const int chunk = (EE + TW - 1) / TW;

    // which codes: 0 -> g_h0, 1 -> g_h1, 2 -> passed pointer
    // layer 0: x(input) -> h0
    k_root   <<<512, 256>>>(x, 2, w0_root, b0, nullptr, 0);
    k_edge_bd<<<EBLOCKS, 256>>>(x, 2, w0_rel, nullptr, 0, chunk);
    k_relu   <<<832, 256>>>(0);
    // layer 1: h0 -> h1
    k_root   <<<512, 256>>>(nullptr, 0, w1_root, b1, nullptr, 1);
    k_edge_bd<<<EBLOCKS, 256>>>(nullptr, 0, w1_rel, nullptr, 1, chunk);
    k_relu   <<<832, 256>>>(1);
    // layer 2: h1 -> out (no relu)
    k_root     <<<512, 256>>>(nullptr, 1, w2_root, b2, out, 2);
    k_edge_full<<<EBLOCKS, 256>>>(nullptr, 1, w2_rel, out, 2, chunk);
}

// round 5
// speedup vs baseline: 1.0166x; 1.0166x over previous
#include <cuda_runtime.h>
#include <cstdint>

#define NN 50000     // nodes
#define HD 64        // hidden = out
#define RR 50        // relations
#define EE 800000    // edges
#define NB 4         // blocks (block-diagonal)
#define DB 16        // block dim
#define SC_CH 2048   // edges per scatter block

// ---------------- scratch (device globals; no allocation allowed) ----------------
__device__ int   g_cnt[NN * RR];      // per (dst,rel) edge counts
__device__ int   g_hist[RR];          // relation histogram
__device__ int   g_cursor[RR];        // scatter cursors (prefix bases, bumped per block)
__device__ int4  g_ep[EE];            // relation-sorted edges: {src, dst, rel, scale_bits}
__device__ float g_h0[NN * HD];
__device__ float g_h1[NN * HD];

typedef unsigned long long u64;

// Device-side buffer selection (keeps kernel_launch free of runtime API calls).
__device__ __forceinline__ float* pick_buf(int which, float* io) {
    return which == 0 ? g_h0 : (which == 1 ? g_h1 : io);
}
__device__ __forceinline__ const float* pick_cbuf(int which, const float* io) {
    return which == 0 ? g_h0 : (which == 1 ? g_h1 : io);
}

__device__ __forceinline__ u64 f2pack(float a, float b) {
    u64 r; asm("mov.b64 %0,{%1,%2};" : "=l"(r) : "f"(a), "f"(b)); return r;
}
__device__ __forceinline__ u64 f2dup(float a) {
    u64 r; asm("mov.b64 %0,{%1,%1};" : "=l"(r) : "f"(a)); return r;
}
__device__ __forceinline__ u64 f2fma(u64 a, u64 b, u64 c) {
    u64 d; asm("fma.rn.f32x2 %0,%1,%2,%3;" : "=l"(d) : "l"(a), "l"(b), "l"(c)); return d;
}
__device__ __forceinline__ u64 f2mul(u64 a, u64 b) {
    u64 d; asm("mul.rn.f32x2 %0,%1,%2;" : "=l"(d) : "l"(a), "l"(b)); return d;
}
__device__ __forceinline__ u64 f2add(u64 a, u64 b) {
    u64 d; asm("add.rn.f32x2 %0,%1,%2;" : "=l"(d) : "l"(a), "l"(b)); return d;
}
__device__ __forceinline__ void f2unpack(u64 v, float& a, float& b) {
    asm("mov.b64 {%0,%1},%2;" : "=f"(a), "=f"(b) : "l"(v));
}
__device__ __forceinline__ void red2(float* p, float a, float b) {
    asm volatile("red.global.add.v2.f32 [%0],{%1,%2};" :: "l"(p), "f"(a), "f"(b) : "memory");
}
__device__ __forceinline__ void pf_l1(const void* p) {
    asm volatile("prefetch.global.L1 [%0];" :: "l"(p));
}

// ---------------- setup kernels ----------------
__global__ void k_zero() {
    int i = blockIdx.x * blockDim.x + threadIdx.x;
    int stride = gridDim.x * blockDim.x;
    int4* p = (int4*)g_cnt;
    const int n4 = (NN * RR) / 4;           // 2,500,000 / 4
    for (int j = i; j < n4; j += stride) p[j] = make_int4(0, 0, 0, 0);
    if (i < RR) g_hist[i] = 0;
}

// 4 edges per thread (int4 loads) for MLP; shared relation histogram per block.
__global__ void __launch_bounds__(512) k_count(const int* __restrict__ dst,
                                               const int* __restrict__ et) {
    __shared__ int sh[RR];
    for (int i = threadIdx.x; i < RR; i += blockDim.x) sh[i] = 0;
    __syncthreads();
    const int4* d4 = (const int4*)dst;
    const int4* r4 = (const int4*)et;
    int i = blockIdx.x * blockDim.x + threadIdx.x;
    int stride = gridDim.x * blockDim.x;
    for (; i < EE / 4; i += stride) {
        int4 d = __ldg(d4 + i);
        int4 r = __ldg(r4 + i);
        atomicAdd(&g_cnt[d.x * RR + r.x], 1);
        atomicAdd(&g_cnt[d.y * RR + r.y], 1);
        atomicAdd(&g_cnt[d.z * RR + r.z], 1);
        atomicAdd(&g_cnt[d.w * RR + r.w], 1);
        atomicAdd(&sh[r.x], 1);
        atomicAdd(&sh[r.y], 1);
        atomicAdd(&sh[r.z], 1);
        atomicAdd(&sh[r.w], 1);
    }
    __syncthreads();
    for (int i2 = threadIdx.x; i2 < RR; i2 += blockDim.x) atomicAdd(&g_hist[i2], sh[i2]);
}

__global__ void k_scan() {
    int off = 0;
    for (int r = 0; r < RR; r++) { g_cursor[r] = off; off += g_hist[r]; }
}

// Block-aggregated counting-sort scatter: one block owns a contiguous edge chunk,
// reserves per-relation subranges with ONE global atomic per (block, relation).
__global__ void __launch_bounds__(512) k_scatter(const int* __restrict__ src,
                                                 const int* __restrict__ dst,
                                                 const int* __restrict__ et) {
    __shared__ int shh[RR];
    __shared__ int shb[RR];
    int base = blockIdx.x * SC_CH;
    int end = base + SC_CH; if (end > EE) end = EE;

    for (int i = threadIdx.x; i < RR; i += blockDim.x) shh[i] = 0;
    __syncthreads();
    for (int e = base + threadIdx.x; e < end; e += blockDim.x)
        atomicAdd(&shh[__ldg(et + e)], 1);
    __syncthreads();
    for (int r = threadIdx.x; r < RR; r += blockDim.x) {
        shb[r] = atomicAdd(&g_cursor[r], shh[r]);
        shh[r] = 0;
    }
    __syncthreads();
    for (int e = base + threadIdx.x; e < end; e += blockDim.x) {
        int r = __ldg(et + e);
        int p = shb[r] + atomicAdd(&shh[r], 1);
        int d = __ldg(dst + e);
        int c = __ldg(&g_cnt[d * RR + r]);
        float sc = 1.0f / (float)(c > 1 ? c : 1);
        g_ep[p] = make_int4(__ldg(src + e), d, r, __float_as_int(sc));
    }
}

// ---------------- root GEMM: out[n,:] = x[n,:] @ W(64x64) + bias ----------------
__global__ void __launch_bounds__(128) k_root(const float* __restrict__ xio, int wx,
                                              const float* __restrict__ w,
                                              const float* __restrict__ bias,
                                              float* __restrict__ oio, int wo) {
    const float* x = pick_cbuf(wx, xio);
    float* out = pick_buf(wo, oio);
    int gw = (blockIdx.x * blockDim.x + threadIdx.x) >> 5;
    int lane = threadIdx.x & 31;
    int nwarps = (gridDim.x * blockDim.x) >> 5;

    u64 wreg[64];
#pragma unroll
    for (int d = 0; d < 64; d++) {
        float2 wv = __ldg((const float2*)(w + (size_t)d * 64 + 2 * lane));
        wreg[d] = f2pack(wv.x, wv.y);
    }
    float2 bv = __ldg((const float2*)(bias + 2 * lane));
    u64 b2 = f2pack(bv.x, bv.y);

    for (int n = gw; n < NN; n += nwarps) {
        const float4* xr = (const float4*)(x + (size_t)n * 64);
        u64 a0 = b2, a1 = 0ull, a2 = 0ull, a3 = 0ull;
#pragma unroll
        for (int t = 0; t < 16; t += 4) {
            float4 q0 = xr[t + 0], q1 = xr[t + 1], q2 = xr[t + 2], q3 = xr[t + 3];
            a0 = f2fma(wreg[4 * t + 0],  f2dup(q0.x), a0);
            a1 = f2fma(wreg[4 * t + 1],  f2dup(q0.y), a1);
            a2 = f2fma(wreg[4 * t + 2],  f2dup(q0.z), a2);
            a3 = f2fma(wreg[4 * t + 3],  f2dup(q0.w), a3);
            a0 = f2fma(wreg[4 * t + 4],  f2dup(q1.x), a0);
            a1 = f2fma(wreg[4 * t + 5],  f2dup(q1.y), a1);
            a2 = f2fma(wreg[4 * t + 6],  f2dup(q1.z), a2);
            a3 = f2fma(wreg[4 * t + 7],  f2dup(q1.w), a3);
            a0 = f2fma(wreg[4 * t + 8],  f2dup(q2.x), a0);
            a1 = f2fma(wreg[4 * t + 9],  f2dup(q2.y), a1);
            a2 = f2fma(wreg[4 * t + 10], f2dup(q2.z), a2);
            a3 = f2fma(wreg[4 * t + 11], f2dup(q2.w), a3);
            a0 = f2fma(wreg[4 * t + 12], f2dup(q3.x), a0);
            a1 = f2fma(wreg[4 * t + 13], f2dup(q3.y), a1);
            a2 = f2fma(wreg[4 * t + 14], f2dup(q3.z), a2);
            a3 = f2fma(wreg[4 * t + 15], f2dup(q3.w), a3);
        }
        u64 acc = f2add(f2add(a0, a1), f2add(a2, a3));
        float a, b; f2unpack(acc, a, b);
        *(float2*)(out + (size_t)n * 64 + 2 * lane) = make_float2(a, b);
    }
}

// ---------------- edge transform + scatter, block-diagonal W [R,4,16,16] ----------------
__global__ void __launch_bounds__(128) k_edge_bd(const float* __restrict__ xio, int wx,
                                                 const float* __restrict__ wrel,
                                                 float* __restrict__ oio, int wo, int chunk) {
    const float* x = pick_cbuf(wx, xio);
    float* out = pick_buf(wo, oio);
    int gw = (blockIdx.x * blockDim.x + threadIdx.x) >> 5;
    int lane = threadIdx.x & 31;
    long e0 = (long)gw * chunk;
    if (e0 >= EE) return;
    int e1 = (int)e0 + chunk; if (e1 > EE) e1 = EE;

    int b = lane >> 3;             // block 0..3 (outputs 2l,2l+1 live in block b)
    int col = (2 * lane) & 15;     // column within block
    u64 wreg[16];
    int prev = -1;

    for (int e = (int)e0; e < e1; e++) {
        int4 ep = __ldg(&g_ep[e]);
        if (ep.z != prev) {
            prev = ep.z;
            const float* wb = wrel + ((size_t)ep.z * NB + b) * 256 + col;
#pragma unroll
            for (int d = 0; d < 16; d++) {
                float2 wv = __ldg((const float2*)(wb + d * 16));
                wreg[d] = f2pack(wv.x, wv.y);
            }
        }
        if (e + 1 < e1) {
            int sn = __ldg(&g_ep[e + 1].x);
            const char* nx = (const char*)(x + (size_t)sn * 64);
            pf_l1(nx); pf_l1(nx + 128);
        }
        const float4* xr = (const float4*)(x + (size_t)ep.x * 64) + b * 4;
        float4 q0 = xr[0], q1 = xr[1], q2 = xr[2], q3 = xr[3];
        u64 a0 = 0ull, a1 = 0ull;
        a0 = f2fma(wreg[0],  f2dup(q0.x), a0);
        a1 = f2fma(wreg[1],  f2dup(q0.y), a1);
        a0 = f2fma(wreg[2],  f2dup(q0.z), a0);
        a1 = f2fma(wreg[3],  f2dup(q0.w), a1);
        a0 = f2fma(wreg[4],  f2dup(q1.x), a0);
        a1 = f2fma(wreg[5],  f2dup(q1.y), a1);
        a0 = f2fma(wreg[6],  f2dup(q1.z), a0);
        a1 = f2fma(wreg[7],  f2dup(q1.w), a1);
        a0 = f2fma(wreg[8],  f2dup(q2.x), a0);
        a1 = f2fma(wreg[9],  f2dup(q2.y), a1);
        a0 = f2fma(wreg[10], f2dup(q2.z), a0);
        a1 = f2fma(wreg[11], f2dup(q2.w), a1);
        a0 = f2fma(wreg[12], f2dup(q3.x), a0);
        a1 = f2fma(wreg[13], f2dup(q3.y), a1);
        a0 = f2fma(wreg[14], f2dup(q3.z), a0);
        a1 = f2fma(wreg[15], f2dup(q3.w), a1);
        u64 acc = f2mul(f2add(a0, a1), f2dup(__int_as_float(ep.w)));
        float a, bb; f2unpack(acc, a, bb);
        red2(out + (size_t)ep.y * 64 + 2 * lane, a, bb);
    }
}

// ---------------- edge transform + scatter, full W [R,64,64] ----------------
__global__ void __launch_bounds__(128) k_edge_full(const float* __restrict__ xio, int wx,
                                                   const float* __restrict__ wrel,
                                                   float* __restrict__ oio, int wo, int chunk) {
    const float* x = pick_cbuf(wx, xio);
    float* out = pick_buf(wo, oio);
    int gw = (blockIdx.x * blockDim.x + threadIdx.x) >> 5;
    int lane = threadIdx.x & 31;
    long e0 = (long)gw * chunk;
    if (e0 >= EE) return;
    int e1 = (int)e0 + chunk; if (e1 > EE) e1 = EE;

    u64 wreg[64];
    int prev = -1;

    for (int e = (int)e0; e < e1; e++) {
        int4 ep = __ldg(&g_ep[e]);
        if (ep.z != prev) {
            prev = ep.z;
            const float* wb = wrel + (size_t)ep.z * 4096 + 2 * lane;
#pragma unroll
            for (int d = 0; d < 64; d++) {
                float2 wv = __ldg((const float2*)(wb + (size_t)d * 64));
                wreg[d] = f2pack(wv.x, wv.y);
            }
        }
        if (e + 1 < e1) {
            int sn = __ldg(&g_ep[e + 1].x);
            const char* nx = (const char*)(x + (size_t)sn * 64);
            pf_l1(nx); pf_l1(nx + 128);
        }
        const float4* xr = (const float4*)(x + (size_t)ep.x * 64);
        u64 a0 = 0ull, a1 = 0ull, a2 = 0ull, a3 = 0ull;
#pragma unroll
        for (int t = 0; t < 16; t += 4) {
            float4 q0 = xr[t + 0], q1 = xr[t + 1], q2 = xr[t + 2], q3 = xr[t + 3];
            a0 = f2fma(wreg[4 * t + 0],  f2dup(q0.x), a0);
            a1 = f2fma(wreg[4 * t + 1],  f2dup(q0.y), a1);
            a2 = f2fma(wreg[4 * t + 2],  f2dup(q0.z), a2);
            a3 = f2fma(wreg[4 * t + 3],  f2dup(q0.w), a3);
            a0 = f2fma(wreg[4 * t + 4],  f2dup(q1.x), a0);
            a1 = f2fma(wreg[4 * t + 5],  f2dup(q1.y), a1);
            a2 = f2fma(wreg[4 * t + 6],  f2dup(q1.z), a2);
            a3 = f2fma(wreg[4 * t + 7],  f2dup(q1.w), a3);
            a0 = f2fma(wreg[4 * t + 8],  f2dup(q2.x), a0);
            a1 = f2fma(wreg[4 * t + 9],  f2dup(q2.y), a1);
            a2 = f2fma(wreg[4 * t + 10], f2dup(q2.z), a2);
            a3 = f2fma(wreg[4 * t + 11], f2dup(q2.w), a3);
            a0 = f2fma(wreg[4 * t + 12], f2dup(q3.x), a0);
            a1 = f2fma(wreg[4 * t + 13], f2dup(q3.y), a1);
            a2 = f2fma(wreg[4 * t + 14], f2dup(q3.z), a2);
            a3 = f2fma(wreg[4 * t + 15], f2dup(q3.w), a3);
        }
        u64 acc = f2mul(f2add(f2add(a0, a1), f2add(a2, a3)), f2dup(__int_as_float(ep.w)));
        float a, bb; f2unpack(acc, a, bb);
        red2(out + (size_t)ep.y * 64 + 2 * lane, a, bb);
    }
}

__global__ void k_relu(int which) {
    float* h = pick_buf(which, nullptr);
    int i = blockIdx.x * blockDim.x + threadIdx.x;
    int stride = gridDim.x * blockDim.x;
    float4* p = (float4*)h;
    for (; i < NN * HD / 4; i += stride) {
        float4 v = p[i];
        v.x = fmaxf(v.x, 0.f); v.y = fmaxf(v.y, 0.f);
        v.z = fmaxf(v.z, 0.f); v.w = fmaxf(v.w, 0.f);
        p[i] = v;
    }
}

// ---------------- host ----------------
extern "C" void kernel_launch(void* const* d_in, const int* in_sizes, int n_in,
                              void* d_out, int out_size) {
    const float* x       = (const float*)d_in[0];
    const int*   eidx    = (const int*)d_in[1];
    const int*   src     = eidx;
    const int*   dst     = eidx + EE;
    const int*   et      = (const int*)d_in[2];
    const float* w0_rel  = (const float*)d_in[3];
    const float* w0_root = (const float*)d_in[4];
    const float* b0      = (const float*)d_in[5];
    const float* w1_rel  = (const float*)d_in[6];
    const float* w1_root = (const float*)d_in[7];
    const float* b1      = (const float*)d_in[8];
    const float* w2_rel  = (const float*)d_in[9];
    const float* w2_root = (const float*)d_in[10];
    const float* b2      = (const float*)d_in[11];
    float* out = (float*)d_out;

    // setup: counts + relation counting-sort (block-aggregated)
    k_zero<<<1280, 512>>>();
    k_count<<<400, 512>>>(dst, et);
    k_scan<<<1, 1>>>();
    const int SC_BLOCKS = (EE + SC_CH - 1) / SC_CH;     // 391
    k_scatter<<<SC_BLOCKS, 512>>>(src, dst, et);

    // edge-kernel geometry: contiguous chunk per warp over relation-sorted edges
    const int EBLOCKS = 2368;                 // 4 warps/block (128 threads)
    const int TW = EBLOCKS * 4;               // 9472 warps
    const int chunk = (EE + TW - 1) / TW;     // ~85 edges/warp

    // which codes: 0 -> g_h0, 1 -> g_h1, 2 -> passed pointer
    // layer 0: x(input) -> h0
    k_root   <<<1024, 128>>>(x, 2, w0_root, b0, nullptr, 0);
    k_edge_bd<<<EBLOCKS, 128>>>(x, 2, w0_rel, nullptr, 0, chunk);
    k_relu   <<<832, 256>>>(0);
    // layer 1: h0 -> h1
    k_root   <<<1024, 128>>>(nullptr, 0, w1_root, b1, nullptr, 1);
    k_edge_bd<<<EBLOCKS, 128>>>(nullptr, 0, w1_rel, nullptr, 1, chunk);
    k_relu   <<<832, 256>>>(1);
    // layer 2: h1 -> out (no relu)
    k_root     <<<1024, 128>>>(nullptr, 1, w2_root, b2, out, 2);
    k_edge_full<<<EBLOCKS, 128>>>(nullptr, 1, w2_rel, out, 2, chunk);
}

// round 6
// speedup vs baseline: 1.3385x; 1.3167x over previous
#include <cuda_runtime.h>
#include <cstdint>

#define NN 50000     // nodes
#define HD 64        // hidden = out
#define RR 50        // relations
#define EE 800000    // edges
#define NB 4         // blocks (block-diagonal)
#define SC_CH 2048   // edges per scatter block

// ---------------- scratch (device globals; no allocation allowed) ----------------
__device__ int   g_cnt[NN * RR];      // per (dst,rel) edge counts
__device__ int   g_hist[RR];          // relation histogram
__device__ int   g_cursor[RR];        // scatter cursors (prefix bases)
__device__ int   g_done;              // k_count completion counter
__device__ int4  g_ep[EE];            // relation-sorted edges: {src, dst, rel, scale_bits}
__device__ float g_h0[NN * HD];
__device__ float g_h1[NN * HD];

typedef unsigned long long u64;

__device__ __forceinline__ float* pick_buf(int which, float* io) {
    return which == 0 ? g_h0 : (which == 1 ? g_h1 : io);
}
__device__ __forceinline__ const float* pick_cbuf(int which, const float* io) {
    return which == 0 ? g_h0 : (which == 1 ? g_h1 : io);
}

__device__ __forceinline__ u64 f2pack(float a, float b) {
    u64 r; asm("mov.b64 %0,{%1,%2};" : "=l"(r) : "f"(a), "f"(b)); return r;
}
__device__ __forceinline__ u64 f2fma(u64 a, u64 b, u64 c) {
    u64 d; asm("fma.rn.f32x2 %0,%1,%2,%3;" : "=l"(d) : "l"(a), "l"(b), "l"(c)); return d;
}
__device__ __forceinline__ void f2unpack(u64 v, float& a, float& b) {
    asm("mov.b64 {%0,%1},%2;" : "=f"(a), "=f"(b) : "l"(v));
}
__device__ __forceinline__ void red2(float* p, float a, float b) {
    asm volatile("red.global.add.v2.f32 [%0],{%1,%2};" :: "l"(p), "f"(a), "f"(b) : "memory");
}
__device__ __forceinline__ float hadd_u64(u64 v) {
    float a, b; f2unpack(v, a, b); return a + b;
}

// ---------------- setup kernels ----------------
__global__ void k_zero(float* __restrict__ out) {
    int i = blockIdx.x * blockDim.x + threadIdx.x;
    int stride = gridDim.x * blockDim.x;
    int4* p = (int4*)g_cnt;
    const int n4 = (NN * RR) / 4;
    for (int j = i; j < n4; j += stride) p[j] = make_int4(0, 0, 0, 0);
    float4 z4 = make_float4(0.f, 0.f, 0.f, 0.f);
    float4* h0 = (float4*)g_h0;
    float4* h1 = (float4*)g_h1;
    float4* o4 = (float4*)out;
    const int m4 = (NN * HD) / 4;
    for (int j = i; j < m4; j += stride) { h0[j] = z4; h1[j] = z4; o4[j] = z4; }
    if (i < RR) g_hist[i] = 0;
    if (i == RR) g_done = 0;
}

// 4 edges per thread (int4 loads); shared relation histogram; last block scans.
__global__ void __launch_bounds__(512) k_count(const int* __restrict__ dst,
                                               const int* __restrict__ et) {
    __shared__ int sh[RR];
    __shared__ bool last;
    for (int i = threadIdx.x; i < RR; i += blockDim.x) sh[i] = 0;
    __syncthreads();
    const int4* d4 = (const int4*)dst;
    const int4* r4 = (const int4*)et;
    int i = blockIdx.x * blockDim.x + threadIdx.x;
    int stride = gridDim.x * blockDim.x;
    for (; i < EE / 4; i += stride) {
        int4 d = __ldg(d4 + i);
        int4 r = __ldg(r4 + i);
        atomicAdd(&g_cnt[d.x * RR + r.x], 1);
        atomicAdd(&g_cnt[d.y * RR + r.y], 1);
        atomicAdd(&g_cnt[d.z * RR + r.z], 1);
        atomicAdd(&g_cnt[d.w * RR + r.w], 1);
        atomicAdd(&sh[r.x], 1);
        atomicAdd(&sh[r.y], 1);
        atomicAdd(&sh[r.z], 1);
        atomicAdd(&sh[r.w], 1);
    }
    __syncthreads();
    for (int j = threadIdx.x; j < RR; j += blockDim.x) atomicAdd(&g_hist[j], sh[j]);
    // fused exclusive scan: last block to finish writes g_cursor
    if (threadIdx.x == 0) {
        __threadfence();
        int t = atomicAdd(&g_done, 1);
        last = (t == (int)gridDim.x - 1);
    }
    __syncthreads();
    if (last && threadIdx.x == 0) {
        __threadfence();
        int off = 0;
        for (int r = 0; r < RR; r++) { g_cursor[r] = off; off += g_hist[r]; }
    }
}

// Block-aggregated counting-sort scatter: one global atomic per (block, relation).
__global__ void __launch_bounds__(512) k_scatter(const int* __restrict__ src,
                                                 const int* __restrict__ dst,
                                                 const int* __restrict__ et) {
    __shared__ int shh[RR];
    __shared__ int shb[RR];
    int base = blockIdx.x * SC_CH;
    int end = base + SC_CH; if (end > EE) end = EE;

    for (int i = threadIdx.x; i < RR; i += blockDim.x) shh[i] = 0;
    __syncthreads();
    for (int e = base + threadIdx.x; e < end; e += blockDim.x)
        atomicAdd(&shh[__ldg(et + e)], 1);
    __syncthreads();
    for (int r = threadIdx.x; r < RR; r += blockDim.x) {
        shb[r] = atomicAdd(&g_cursor[r], shh[r]);
        shh[r] = 0;
    }
    __syncthreads();
    for (int e = base + threadIdx.x; e < end; e += blockDim.x) {
        int r = __ldg(et + e);
        int p = shb[r] + atomicAdd(&shh[r], 1);
        int d = __ldg(dst + e);
        int c = __ldg(&g_cnt[d * RR + r]);
        float sc = 1.0f / (float)(c > 1 ? c : 1);
        g_ep[p] = make_int4(__ldg(src + e), d, r, __float_as_int(sc));
    }
}

// ---------------- edge transform + scatter, block-diagonal W [R,4,16,16] ----------------
// d-pair packing: acc{lo,hi} += {x[2t],x[2t+1]} * {W[2t,c],W[2t+1,c]}; result = lo+hi.
__global__ void __launch_bounds__(128) k_edge_bd(const float* __restrict__ xio, int wx,
                                                 const float* __restrict__ wrel,
                                                 float* __restrict__ oio, int wo, int chunk) {
    const float* x = pick_cbuf(wx, xio);
    float* out = pick_buf(wo, oio);
    int gw = (blockIdx.x * blockDim.x + threadIdx.x) >> 5;
    int lane = threadIdx.x & 31;
    long e0l = (long)gw * chunk;
    if (e0l >= EE) return;
    int e0 = (int)e0l, e1 = e0 + chunk; if (e1 > EE) e1 = EE;

    int b  = lane >> 3;        // diag block 0..3; global cols 2l,2l+1 live in block b
    int cb = 2 * (lane & 7);   // column within block
    u64 w0[8], w1[8];          // packed d-pairs for col cb, cb+1
    int prev = -1;

#pragma unroll 2
    for (int e = e0; e < e1; e++) {
        int4 ep = __ldg(&g_ep[e]);
        if (ep.z != prev) {
            prev = ep.z;
            const float* wb = wrel + ((size_t)ep.z * NB + b) * 256;
#pragma unroll
            for (int t = 0; t < 8; t++) {
                w0[t] = f2pack(__ldg(wb + (2 * t) * 16 + cb),
                               __ldg(wb + (2 * t + 1) * 16 + cb));
                w1[t] = f2pack(__ldg(wb + (2 * t) * 16 + cb + 1),
                               __ldg(wb + (2 * t + 1) * 16 + cb + 1));
            }
        }
        const ulonglong2* xr = (const ulonglong2*)(x + (size_t)ep.x * 64 + b * 16);
        ulonglong2 p0 = xr[0], p1 = xr[1], p2 = xr[2], p3 = xr[3];
        u64 a0 = 0ull, a1 = 0ull;
        a0 = f2fma(p0.x, w0[0], a0);  a1 = f2fma(p0.x, w1[0], a1);
        a0 = f2fma(p0.y, w0[1], a0);  a1 = f2fma(p0.y, w1[1], a1);
        a0 = f2fma(p1.x, w0[2], a0);  a1 = f2fma(p1.x, w1[2], a1);
        a0 = f2fma(p1.y, w0[3], a0);  a1 = f2fma(p1.y, w1[3], a1);
        a0 = f2fma(p2.x, w0[4], a0);  a1 = f2fma(p2.x, w1[4], a1);
        a0 = f2fma(p2.y, w0[5], a0);  a1 = f2fma(p2.y, w1[5], a1);
        a0 = f2fma(p3.x, w0[6], a0);  a1 = f2fma(p3.x, w1[6], a1);
        a0 = f2fma(p3.y, w0[7], a0);  a1 = f2fma(p3.y, w1[7], a1);
        float sc = __int_as_float(ep.w);
        float r0 = hadd_u64(a0) * sc;
        float r1 = hadd_u64(a1) * sc;
        red2(out + (size_t)ep.y * 64 + 2 * lane, r0, r1);
    }
}

// ---------------- edge transform + scatter, full W [R,64,64] ----------------
__global__ void __launch_bounds__(128) k_edge_full(const float* __restrict__ xio, int wx,
                                                   const float* __restrict__ wrel,
                                                   float* __restrict__ oio, int wo, int chunk) {
    const float* x = pick_cbuf(wx, xio);
    float* out = pick_buf(wo, oio);
    int gw = (blockIdx.x * blockDim.x + threadIdx.x) >> 5;
    int lane = threadIdx.x & 31;
    long e0l = (long)gw * chunk;
    if (e0l >= EE) return;
    int e0 = (int)e0l, e1 = e0 + chunk; if (e1 > EE) e1 = EE;

    int c0 = 2 * lane;         // this lane's output cols: c0, c0+1
    u64 w0[32], w1[32];        // packed d-pairs for each col
    int prev = -1;

    for (int e = e0; e < e1; e++) {
        int4 ep = __ldg(&g_ep[e]);
        if (ep.z != prev) {
            prev = ep.z;
            const float* wb = wrel + (size_t)ep.z * 4096;
#pragma unroll
            for (int t = 0; t < 32; t++) {
                w0[t] = f2pack(__ldg(wb + (2 * t) * 64 + c0),
                               __ldg(wb + (2 * t + 1) * 64 + c0));
                w1[t] = f2pack(__ldg(wb + (2 * t) * 64 + c0 + 1),
                               __ldg(wb + (2 * t + 1) * 64 + c0 + 1));
            }
        }
        const ulonglong2* xr = (const ulonglong2*)(x + (size_t)ep.x * 64);
        u64 a0 = 0ull, b0a = 0ull, a1 = 0ull, b1a = 0ull;   // 4 chains
#pragma unroll
        for (int q = 0; q < 4; q++) {
            ulonglong2 pA = xr[2 * q], pB = xr[2 * q + 1];
            int t = 4 * q;
            a0  = f2fma(pA.x, w0[t + 0], a0);
            a1  = f2fma(pA.x, w1[t + 0], a1);
            b0a = f2fma(pA.y, w0[t + 1], b0a);
            b1a = f2fma(pA.y, w1[t + 1], b1a);
            a0  = f2fma(pB.x, w0[t + 2], a0);
            a1  = f2fma(pB.x, w1[t + 2], a1);
            b0a = f2fma(pB.y, w0[t + 3], b0a);
            b1a = f2fma(pB.y, w1[t + 3], b1a);
        }
#pragma unroll
        for (int q = 4; q < 8; q++) {
            ulonglong2 pA = xr[2 * q], pB = xr[2 * q + 1];
            int t = 4 * q;
            a0  = f2fma(pA.x, w0[t + 0], a0);
            a1  = f2fma(pA.x, w1[t + 0], a1);
            b0a = f2fma(pA.y, w0[t + 1], b0a);
            b1a = f2fma(pA.y, w1[t + 1], b1a);
            a0  = f2fma(pB.x, w0[t + 2], a0);
            a1  = f2fma(pB.x, w1[t + 2], a1);
            b0a = f2fma(pB.y, w0[t + 3], b0a);
            b1a = f2fma(pB.y, w1[t + 3], b1a);
        }
        float sc = __int_as_float(ep.w);
        float r0 = (hadd_u64(a0) + hadd_u64(b0a)) * sc;
        float r1 = (hadd_u64(a1) + hadd_u64(b1a)) * sc;
        red2(out + (size_t)ep.y * 64 + c0, r0, r1);
    }
}

// ---------------- root GEMM (accumulate): out[n,:] += x[n,:] @ W + bias ----------------
__global__ void __launch_bounds__(128) k_root_add(const float* __restrict__ xio, int wx,
                                                  const float* __restrict__ w,
                                                  const float* __restrict__ bias,
                                                  float* __restrict__ oio, int wo) {
    const float* x = pick_cbuf(wx, xio);
    float* out = pick_buf(wo, oio);
    int gw = (blockIdx.x * blockDim.x + threadIdx.x) >> 5;
    int lane = threadIdx.x & 31;
    int nwarps = (gridDim.x * blockDim.x) >> 5;
    int c0 = 2 * lane;

    u64 w0[32], w1[32];
#pragma unroll
    for (int t = 0; t < 32; t++) {
        w0[t] = f2pack(__ldg(w + (2 * t) * 64 + c0),
                       __ldg(w + (2 * t + 1) * 64 + c0));
        w1[t] = f2pack(__ldg(w + (2 * t) * 64 + c0 + 1),
                       __ldg(w + (2 * t + 1) * 64 + c0 + 1));
    }
    float bx = __ldg(bias + c0), by = __ldg(bias + c0 + 1);

    for (int n = gw; n < NN; n += nwarps) {
        const ulonglong2* xr = (const ulonglong2*)(x + (size_t)n * 64);
        u64 a0 = 0ull, b0a = 0ull, a1 = 0ull, b1a = 0ull;
#pragma unroll
        for (int q = 0; q < 8; q++) {
            ulonglong2 pA = xr[2 * q], pB = xr[2 * q + 1];
            int t = 4 * q;
            a0  = f2fma(pA.x, w0[t + 0], a0);
            a1  = f2fma(pA.x, w1[t + 0], a1);
            b0a = f2fma(pA.y, w0[t + 1], b0a);
            b1a = f2fma(pA.y, w1[t + 1], b1a);
            a0  = f2fma(pB.x, w0[t + 2], a0);
            a1  = f2fma(pB.x, w1[t + 2], a1);
            b0a = f2fma(pB.y, w0[t + 3], b0a);
            b1a = f2fma(pB.y, w1[t + 3], b1a);
        }
        float2* op = (float2*)(out + (size_t)n * 64 + c0);
        float2 cur = *op;
        cur.x += hadd_u64(a0) + hadd_u64(b0a) + bx;
        cur.y += hadd_u64(a1) + hadd_u64(b1a) + by;
        *op = cur;
    }
}

__global__ void k_relu(int which) {
    float* h = pick_buf(which, nullptr);
    int i = blockIdx.x * blockDim.x + threadIdx.x;
    int stride = gridDim.x * blockDim.x;
    float4* p = (float4*)h;
    for (; i < NN * HD / 4; i += stride) {
        float4 v = p[i];
        v.x = fmaxf(v.x, 0.f); v.y = fmaxf(v.y, 0.f);
        v.z = fmaxf(v.z, 0.f); v.w = fmaxf(v.w, 0.f);
        p[i] = v;
    }
}

// ---------------- host ----------------
extern "C" void kernel_launch(void* const* d_in, const int* in_sizes, int n_in,
                              void* d_out, int out_size) {
    const float* x       = (const float*)d_in[0];
    const int*   eidx    = (const int*)d_in[1];
    const int*   src     = eidx;
    const int*   dst     = eidx + EE;
    const int*   et      = (const int*)d_in[2];
    const float* w0_rel  = (const float*)d_in[3];
    const float* w0_root = (const float*)d_in[4];
    const float* b0      = (const float*)d_in[5];
    const float* w1_rel  = (const float*)d_in[6];
    const float* w1_root = (const float*)d_in[7];
    const float* b1      = (const float*)d_in[8];
    const float* w2_rel  = (const float*)d_in[9];
    const float* w2_root = (const float*)d_in[10];
    const float* b2      = (const float*)d_in[11];
    float* out = (float*)d_out;

    // 1: zero everything (cnt/hist/done + h0/h1/out accumulators)
    k_zero<<<1280, 512>>>(out);
    // 2: per-(dst,rel) counts + relation histogram + fused scan
    k_count<<<400, 512>>>(dst, et);
    // 3: block-aggregated counting-sort by relation
    const int SC_BLOCKS = (EE + SC_CH - 1) / SC_CH;     // 391
    k_scatter<<<SC_BLOCKS, 512>>>(src, dst, et);

    const int EBLOCKS = 2368;                 // 4 warps/block
    const int TW = EBLOCKS * 4;
    const int chunk = (EE + TW - 1) / TW;     // ~85 edges/warp

    // layer 0: edges first (into zeroed h0), then root accumulate, then relu
    k_edge_bd <<<EBLOCKS, 128>>>(x, 2, w0_rel, nullptr, 0, chunk);   // launch #4 -> profiled
    k_root_add<<<1024, 128>>>(x, 2, w0_root, b0, nullptr, 0);
    k_relu    <<<832, 256>>>(0);
    // layer 1
    k_edge_bd <<<EBLOCKS, 128>>>(nullptr, 0, w1_rel, nullptr, 1, chunk);
    k_root_add<<<1024, 128>>>(nullptr, 0, w1_root, b1, nullptr, 1);
    k_relu    <<<832, 256>>>(1);
    // layer 2 (no relu)
    k_edge_full<<<EBLOCKS, 128>>>(nullptr, 1, w2_rel, out, 2, chunk);
    k_root_add <<<1024, 128>>>(nullptr, 1, w2_root, b2, out, 2);
}

// round 10
// speedup vs baseline: 1.4104x; 1.0537x over previous
#include <cuda_runtime.h>
#include <cstdint>

#define NN 50000     // nodes
#define HD 64        // hidden = out
#define RR 50        // relations
#define EE 800000    // edges
#define NB 4         // blocks (block-diagonal)
#define SC_CH 2048   // edges per scatter block

// ---------------- scratch (device globals; no allocation allowed) ----------------
__device__ int   g_cnt[NN * RR];      // per (dst,rel) edge counts
__device__ int   g_hist[RR];          // relation histogram
__device__ int   g_cursor[RR];        // scatter cursors (prefix bases)
__device__ int   g_done;              // k_count completion counter
__device__ int4  g_ep[EE];            // relation-sorted edges: {src, dst, rel, scale_bits}
__device__ float g_h0[NN * HD];
__device__ float g_h1[NN * HD];

typedef unsigned long long u64;

__device__ __forceinline__ float* pick_buf(int which, float* io) {
    return which == 0 ? g_h0 : (which == 1 ? g_h1 : io);
}
__device__ __forceinline__ const float* pick_cbuf(int which, const float* io) {
    return which == 0 ? g_h0 : (which == 1 ? g_h1 : io);
}

__device__ __forceinline__ u64 f2pack(float a, float b) {
    u64 r; asm("mov.b64 %0,{%1,%2};" : "=l"(r) : "f"(a), "f"(b)); return r;
}
__device__ __forceinline__ u64 f2fma(u64 a, u64 b, u64 c) {
    u64 d; asm("fma.rn.f32x2 %0,%1,%2,%3;" : "=l"(d) : "l"(a), "l"(b), "l"(c)); return d;
}
__device__ __forceinline__ void f2unpack(u64 v, float& a, float& b) {
    asm("mov.b64 {%0,%1},%2;" : "=f"(a), "=f"(b) : "l"(v));
}
__device__ __forceinline__ void red2(float* p, float a, float b) {
    asm volatile("red.global.add.v2.f32 [%0],{%1,%2};" :: "l"(p), "f"(a), "f"(b) : "memory");
}
__device__ __forceinline__ float hadd_u64(u64 v) {
    float a, b; f2unpack(v, a, b); return a + b;
}

// ---------------- setup kernels ----------------
__global__ void k_zero(float* __restrict__ out) {
    int i = blockIdx.x * blockDim.x + threadIdx.x;
    int stride = gridDim.x * blockDim.x;
    int4* p = (int4*)g_cnt;
    const int n4 = (NN * RR) / 4;
    for (int j = i; j < n4; j += stride) p[j] = make_int4(0, 0, 0, 0);
    float4 z4 = make_float4(0.f, 0.f, 0.f, 0.f);
    float4* h0 = (float4*)g_h0;
    float4* h1 = (float4*)g_h1;
    float4* o4 = (float4*)out;
    const int m4 = (NN * HD) / 4;
    for (int j = i; j < m4; j += stride) { h0[j] = z4; h1[j] = z4; o4[j] = z4; }
    if (i < RR) g_hist[i] = 0;
    if (i == RR) g_done = 0;
}

// 4 edges per thread (int4 loads); shared relation histogram; last block scans.
__global__ void __launch_bounds__(512) k_count(const int* __restrict__ dst,
                                               const int* __restrict__ et) {
    __shared__ int sh[RR];
    __shared__ bool last;
    for (int i = threadIdx.x; i < RR; i += blockDim.x) sh[i] = 0;
    __syncthreads();
    const int4* d4 = (const int4*)dst;
    const int4* r4 = (const int4*)et;
    int i = blockIdx.x * blockDim.x + threadIdx.x;
    int stride = gridDim.x * blockDim.x;
    for (; i < EE / 4; i += stride) {
        int4 d = __ldg(d4 + i);
        int4 r = __ldg(r4 + i);
        atomicAdd(&g_cnt[d.x * RR + r.x], 1);
        atomicAdd(&g_cnt[d.y * RR + r.y], 1);
        atomicAdd(&g_cnt[d.z * RR + r.z], 1);
        atomicAdd(&g_cnt[d.w * RR + r.w], 1);
        atomicAdd(&sh[r.x], 1);
        atomicAdd(&sh[r.y], 1);
        atomicAdd(&sh[r.z], 1);
        atomicAdd(&sh[r.w], 1);
    }
    __syncthreads();
    for (int j = threadIdx.x; j < RR; j += blockDim.x) atomicAdd(&g_hist[j], sh[j]);
    if (threadIdx.x == 0) {
        __threadfence();
        int t = atomicAdd(&g_done, 1);
        last = (t == (int)gridDim.x - 1);
    }
    __syncthreads();
    if (last && threadIdx.x == 0) {
        __threadfence();
        int off = 0;
        for (int r = 0; r < RR; r++) { g_cursor[r] = off; off += g_hist[r]; }
    }
}

// Block-aggregated counting-sort scatter: one global atomic per (block, relation).
__global__ void __launch_bounds__(512) k_scatter(const int* __restrict__ src,
                                                 const int* __restrict__ dst,
                                                 const int* __restrict__ et) {
    __shared__ int shh[RR];
    __shared__ int shb[RR];
    int base = blockIdx.x * SC_CH;
    int end = base + SC_CH; if (end > EE) end = EE;

    for (int i = threadIdx.x; i < RR; i += blockDim.x) shh[i] = 0;
    __syncthreads();
    for (int e = base + threadIdx.x; e < end; e += blockDim.x)
        atomicAdd(&shh[__ldg(et + e)], 1);
    __syncthreads();
    for (int r = threadIdx.x; r < RR; r += blockDim.x) {
        shb[r] = atomicAdd(&g_cursor[r], shh[r]);
        shh[r] = 0;
    }
    __syncthreads();
    for (int e = base + threadIdx.x; e < end; e += blockDim.x) {
        int r = __ldg(et + e);
        int p = shb[r] + atomicAdd(&shh[r], 1);
        int d = __ldg(dst + e);
        int c = __ldg(&g_cnt[d * RR + r]);
        float sc = 1.0f / (float)(c > 1 ? c : 1);
        g_ep[p] = make_int4(__ldg(src + e), d, r, __float_as_int(sc));
    }
}

// ---------------- edge transform + scatter, block-diagonal W [R,4,16,16] ----------------
// 2-edge unroll: two independent ep->x load chains in flight per warp.
__global__ void __launch_bounds__(128) k_edge_bd(const float* __restrict__ xio, int wx,
                                                 const float* __restrict__ wrel,
                                                 float* __restrict__ oio, int wo, int chunk) {
    const float* x = pick_cbuf(wx, xio);
    float* out = pick_buf(wo, oio);
    int gw = (blockIdx.x * blockDim.x + threadIdx.x) >> 5;
    int lane = threadIdx.x & 31;
    long e0l = (long)gw * chunk;
    if (e0l >= EE) return;
    int e0 = (int)e0l, e1 = e0 + chunk; if (e1 > EE) e1 = EE;

    int b  = lane >> 3;        // diag block 0..3; global cols 2l,2l+1 live in block b
    int cb = 2 * (lane & 7);   // column within block
    u64 w0[8], w1[8];
    int prev = -1;

    int e = e0;
    for (; e + 1 < e1; e += 2) {
        int4 epA = __ldg(&g_ep[e]);
        int4 epB = __ldg(&g_ep[e + 1]);
        const ulonglong2* xA = (const ulonglong2*)(x + (size_t)epA.x * 64 + b * 16);
        const ulonglong2* xB = (const ulonglong2*)(x + (size_t)epB.x * 64 + b * 16);
        ulonglong2 pA0 = xA[0], pA1 = xA[1], pA2 = xA[2], pA3 = xA[3];
        ulonglong2 pB0 = xB[0], pB1 = xB[1], pB2 = xB[2], pB3 = xB[3];
        if (epA.z != prev) {
            prev = epA.z;
            const float* wb = wrel + ((size_t)epA.z * NB + b) * 256;
#pragma unroll
            for (int t = 0; t < 8; t++) {
                w0[t] = f2pack(__ldg(wb + (2 * t) * 16 + cb),
                               __ldg(wb + (2 * t + 1) * 16 + cb));
                w1[t] = f2pack(__ldg(wb + (2 * t) * 16 + cb + 1),
                               __ldg(wb + (2 * t + 1) * 16 + cb + 1));
            }
        }
        u64 a0 = 0ull, a1 = 0ull;
        a0 = f2fma(pA0.x, w0[0], a0);  a1 = f2fma(pA0.x, w1[0], a1);
        a0 = f2fma(pA0.y, w0[1], a0);  a1 = f2fma(pA0.y, w1[1], a1);
        a0 = f2fma(pA1.x, w0[2], a0);  a1 = f2fma(pA1.x, w1[2], a1);
        a0 = f2fma(pA1.y, w0[3], a0);  a1 = f2fma(pA1.y, w1[3], a1);
        a0 = f2fma(pA2.x, w0[4], a0);  a1 = f2fma(pA2.x, w1[4], a1);
        a0 = f2fma(pA2.y, w0[5], a0);  a1 = f2fma(pA2.y, w1[5], a1);
        a0 = f2fma(pA3.x, w0[6], a0);  a1 = f2fma(pA3.x, w1[6], a1);
        a0 = f2fma(pA3.y, w0[7], a0);  a1 = f2fma(pA3.y, w1[7], a1);
        float scA = __int_as_float(epA.w);
        red2(out + (size_t)epA.y * 64 + 2 * lane, hadd_u64(a0) * scA, hadd_u64(a1) * scA);

        if (epB.z != prev) {
            prev = epB.z;
            const float* wb = wrel + ((size_t)epB.z * NB + b) * 256;
#pragma unroll
            for (int t = 0; t < 8; t++) {
                w0[t] = f2pack(__ldg(wb + (2 * t) * 16 + cb),
                               __ldg(wb + (2 * t + 1) * 16 + cb));
                w1[t] = f2pack(__ldg(wb + (2 * t) * 16 + cb + 1),
                               __ldg(wb + (2 * t + 1) * 16 + cb + 1));
            }
        }
        u64 c0a = 0ull, c1a = 0ull;
        c0a = f2fma(pB0.x, w0[0], c0a);  c1a = f2fma(pB0.x, w1[0], c1a);
        c0a = f2fma(pB0.y, w0[1], c0a);  c1a = f2fma(pB0.y, w1[1], c1a);
        c0a = f2fma(pB1.x, w0[2], c0a);  c1a = f2fma(pB1.x, w1[2], c1a);
        c0a = f2fma(pB1.y, w0[3], c0a);  c1a = f2fma(pB1.y, w1[3], c1a);
        c0a = f2fma(pB2.x, w0[4], c0a);  c1a = f2fma(pB2.x, w1[4], c1a);
        c0a = f2fma(pB2.y, w0[5], c0a);  c1a = f2fma(pB2.y, w1[5], c1a);
        c0a = f2fma(pB3.x, w0[6], c0a);  c1a = f2fma(pB3.x, w1[6], c1a);
        c0a = f2fma(pB3.y, w0[7], c0a);  c1a = f2fma(pB3.y, w1[7], c1a);
        float scB = __int_as_float(epB.w);
        red2(out + (size_t)epB.y * 64 + 2 * lane, hadd_u64(c0a) * scB, hadd_u64(c1a) * scB);
    }
    for (; e < e1; e++) {
        int4 ep = __ldg(&g_ep[e]);
        if (ep.z != prev) {
            prev = ep.z;
            const float* wb = wrel + ((size_t)ep.z * NB + b) * 256;
#pragma unroll
            for (int t = 0; t < 8; t++) {
                w0[t] = f2pack(__ldg(wb + (2 * t) * 16 + cb),
                               __ldg(wb + (2 * t + 1) * 16 + cb));
                w1[t] = f2pack(__ldg(wb + (2 * t) * 16 + cb + 1),
                               __ldg(wb + (2 * t + 1) * 16 + cb + 1));
            }
        }
        const ulonglong2* xr = (const ulonglong2*)(x + (size_t)ep.x * 64 + b * 16);
        ulonglong2 p0 = xr[0], p1 = xr[1], p2 = xr[2], p3 = xr[3];
        u64 a0 = 0ull, a1 = 0ull;
        a0 = f2fma(p0.x, w0[0], a0);  a1 = f2fma(p0.x, w1[0], a1);
        a0 = f2fma(p0.y, w0[1], a0);  a1 = f2fma(p0.y, w1[1], a1);
        a0 = f2fma(p1.x, w0[2], a0);  a1 = f2fma(p1.x, w1[2], a1);
        a0 = f2fma(p1.y, w0[3], a0);  a1 = f2fma(p1.y, w1[3], a1);
        a0 = f2fma(p2.x, w0[4], a0);  a1 = f2fma(p2.x, w1[4], a1);
        a0 = f2fma(p2.y, w0[5], a0);  a1 = f2fma(p2.y, w1[5], a1);
        a0 = f2fma(p3.x, w0[6], a0);  a1 = f2fma(p3.x, w1[6], a1);
        a0 = f2fma(p3.y, w0[7], a0);  a1 = f2fma(p3.y, w1[7], a1);
        float sc = __int_as_float(ep.w);
        red2(out + (size_t)ep.y * 64 + 2 * lane, hadd_u64(a0) * sc, hadd_u64(a1) * sc);
    }
}

// ---------------- edge transform + scatter, full W [R,64,64], d-split warp pairs --------
// Warp pair shares an edge chunk; warp (dh=0) does d[0:32), (dh=1) d[32:64).
// Both RED into the same outputs — atomics combine the halves.
__global__ void __launch_bounds__(128) k_edge_full(const float* __restrict__ xio, int wx,
                                                   const float* __restrict__ wrel,
                                                   float* __restrict__ oio, int wo, int chunk) {
    const float* x = pick_cbuf(wx, xio);
    float* out = pick_buf(wo, oio);
    int gw = (blockIdx.x * blockDim.x + threadIdx.x) >> 5;
    int lane = threadIdx.x & 31;
    int pair = gw >> 1, dh = gw & 1;
    long e0l = (long)pair * chunk;
    if (e0l >= EE) return;
    int e0 = (int)e0l, e1 = e0 + chunk; if (e1 > EE) e1 = EE;

    int c0 = 2 * lane;
    int d0 = 32 * dh;
    u64 w0[16], w1[16];
    int prev = -1;

    for (int e = e0; e < e1; e++) {
        int4 ep = __ldg(&g_ep[e]);
        if (ep.z != prev) {
            prev = ep.z;
            const float* wb = wrel + (size_t)ep.z * 4096 + (size_t)d0 * 64;
#pragma unroll
            for (int t = 0; t < 16; t++) {
                w0[t] = f2pack(__ldg(wb + (2 * t) * 64 + c0),
                               __ldg(wb + (2 * t + 1) * 64 + c0));
                w1[t] = f2pack(__ldg(wb + (2 * t) * 64 + c0 + 1),
                               __ldg(wb + (2 * t + 1) * 64 + c0 + 1));
            }
        }
        const ulonglong2* xr = (const ulonglong2*)(x + (size_t)ep.x * 64 + d0);
        u64 a0 = 0ull, b0a = 0ull, a1 = 0ull, b1a = 0ull;
#pragma unroll
        for (int q = 0; q < 4; q++) {
            ulonglong2 pA = xr[2 * q], pB = xr[2 * q + 1];
            int t = 4 * q;
            a0  = f2fma(pA.x, w0[t + 0], a0);
            a1  = f2fma(pA.x, w1[t + 0], a1);
            b0a = f2fma(pA.y, w0[t + 1], b0a);
            b1a = f2fma(pA.y, w1[t + 1], b1a);
            a0  = f2fma(pB.x, w0[t + 2], a0);
            a1  = f2fma(pB.x, w1[t + 2], a1);
            b0a = f2fma(pB.y, w0[t + 3], b0a);
            b1a = f2fma(pB.y, w1[t + 3], b1a);
        }
        float sc = __int_as_float(ep.w);
        float r0 = (hadd_u64(a0) + hadd_u64(b0a)) * sc;
        float r1 = (hadd_u64(a1) + hadd_u64(b1a)) * sc;
        red2(out + (size_t)ep.y * 64 + c0, r0, r1);
    }
}

// ---------------- root GEMV (RED-based, d-split warp pairs) ----------------
// out[n,c] += sum_d x[n,d] * W[d,c] (+ bias from dh==0 warp). Buffers pre-zeroed.
__global__ void __launch_bounds__(128) k_root_red(const float* __restrict__ xio, int wx,
                                                  const float* __restrict__ w,
                                                  const float* __restrict__ bias,
                                                  float* __restrict__ oio, int wo) {
    const float* x = pick_cbuf(wx, xio);
    float* out = pick_buf(wo, oio);
    int gw = (blockIdx.x * blockDim.x + threadIdx.x) >> 5;
    int lane = threadIdx.x & 31;
    int pair = gw >> 1, dh = gw & 1;
    int npairs = (gridDim.x * blockDim.x) >> 6;
    int c0 = 2 * lane;
    int d0 = 32 * dh;

    u64 w0[16], w1[16];
    const float* wb = w + (size_t)d0 * 64;
#pragma unroll
    for (int t = 0; t < 16; t++) {
        w0[t] = f2pack(__ldg(wb + (2 * t) * 64 + c0),
                       __ldg(wb + (2 * t + 1) * 64 + c0));
        w1[t] = f2pack(__ldg(wb + (2 * t) * 64 + c0 + 1),
                       __ldg(wb + (2 * t + 1) * 64 + c0 + 1));
    }
    float bx = (dh == 0) ? __ldg(bias + c0) : 0.f;
    float by = (dh == 0) ? __ldg(bias + c0 + 1) : 0.f;

    for (int n = pair; n < NN; n += npairs) {
        const ulonglong2* xr = (const ulonglong2*)(x + (size_t)n * 64 + d0);
        u64 a0 = 0ull, b0a = 0ull, a1 = 0ull, b1a = 0ull;
#pragma unroll
        for (int q = 0; q < 4; q++) {
            ulonglong2 pA = xr[2 * q], pB = xr[2 * q + 1];
            int t = 4 * q;
            a0  = f2fma(pA.x, w0[t + 0], a0);
            a1  = f2fma(pA.x, w1[t + 0], a1);
            b0a = f2fma(pA.y, w0[t + 1], b0a);
            b1a = f2fma(pA.y, w1[t + 1], b1a);
            a0  = f2fma(pB.x, w0[t + 2], a0);
            a1  = f2fma(pB.x, w1[t + 2], a1);
            b0a = f2fma(pB.y, w0[t + 3], b0a);
            b1a = f2fma(pB.y, w1[t + 3], b1a);
        }
        float r0 = hadd_u64(a0) + hadd_u64(b0a) + bx;
        float r1 = hadd_u64(a1) + hadd_u64(b1a) + by;
        red2(out + (size_t)n * 64 + c0, r0, r1);
    }
}

__global__ void k_relu(int which) {
    float* h = pick_buf(which, nullptr);
    int i = blockIdx.x * blockDim.x + threadIdx.x;
    int stride = gridDim.x * blockDim.x;
    float4* p = (float4*)h;
    for (; i < NN * HD / 4; i += stride) {
        float4 v = p[i];
        v.x = fmaxf(v.x, 0.f); v.y = fmaxf(v.y, 0.f);
        v.z = fmaxf(v.z, 0.f); v.w = fmaxf(v.w, 0.f);
        p[i] = v;
    }
}

// ---------------- host ----------------
extern "C" void kernel_launch(void* const* d_in, const int* in_sizes, int n_in,
                              void* d_out, int out_size) {
    const float* x       = (const float*)d_in[0];
    const int*   eidx    = (const int*)d_in[1];
    const int*   src     = eidx;
    const int*   dst     = eidx + EE;
    const int*   et      = (const int*)d_in[2];
    const float* w0_rel  = (const float*)d_in[3];
    const float* w0_root = (const float*)d_in[4];
    const float* b0      = (const float*)d_in[5];
    const float* w1_rel  = (const float*)d_in[6];
    const float* w1_root = (const float*)d_in[7];
    const float* b1      = (const float*)d_in[8];
    const float* w2_rel  = (const float*)d_in[9];
    const float* w2_root = (const float*)d_in[10];
    const float* b2      = (const float*)d_in[11];
    float* out = (float*)d_out;

    k_zero<<<1280, 512>>>(out);
    k_count<<<400, 512>>>(dst, et);
    const int SC_BLOCKS = (EE + SC_CH - 1) / SC_CH;     // 391
    k_scatter<<<SC_BLOCKS, 512>>>(src, dst, et);

    // bd edge kernels: one chunk per warp
    const int EBLOCKS = 2368;
    const int TW = EBLOCKS * 4;
    const int chunk = (EE + TW - 1) / TW;               // ~85

    // full edge kernel: one chunk per warp PAIR
    const int FPAIRS = EBLOCKS * 2;                     // 4736
    const int chunkF = (EE + FPAIRS - 1) / FPAIRS;      // ~169

    // layer 0: edges into zeroed h0, then root accumulate (RED), then relu
    k_edge_bd <<<EBLOCKS, 128>>>(x, 2, w0_rel, nullptr, 0, chunk);   // launch #4 -> profiled
    k_root_red<<<1024, 128>>>(x, 2, w0_root, b0, nullptr, 0);
    k_relu    <<<832, 256>>>(0);
    // layer 1
    k_edge_bd <<<EBLOCKS, 128>>>(nullptr, 0, w1_rel, nullptr, 1, chunk);
    k_root_red<<<1024, 128>>>(nullptr, 0, w1_root, b1, nullptr, 1);
    k_relu    <<<832, 256>>>(1);
    // layer 2 (no relu)
    k_edge_full<<<EBLOCKS, 128>>>(nullptr, 1, w2_rel, out, 2, chunkF);
    k_root_red <<<1024, 128>>>(nullptr, 1, w2_root, b2, out, 2);
}

// round 17
// speedup vs baseline: 1.9003x; 1.3474x over previous
#include <cuda_runtime.h>
#include <cstdint>

#define NN 50000     // nodes
#define HD 64        // hidden = out
#define RR 50        // relations
#define EE 800000    // edges
#define NB 4         // blocks (block-diagonal)
#define SC_CH 2048   // edges per scatter block
#define EB 4         // edges per cp.async batch

// ---------------- scratch (device globals; no allocation allowed) ----------------
__device__ int   g_cnt[NN * RR];
__device__ int   g_hist[RR];
__device__ int   g_cursor[RR];
__device__ int   g_done;
__device__ int4  g_ep[EE];            // relation-sorted: {src, dst, rel, scale_bits}
__device__ float g_h0[NN * HD];
__device__ float g_h1[NN * HD];

typedef unsigned long long u64;

__device__ __forceinline__ float* pick_buf(int which, float* io) {
    return which == 0 ? g_h0 : (which == 1 ? g_h1 : io);
}
__device__ __forceinline__ const float* pick_cbuf(int which, const float* io) {
    return which == 0 ? g_h0 : (which == 1 ? g_h1 : io);
}

__device__ __forceinline__ u64 f2pack(float a, float b) {
    u64 r; asm("mov.b64 %0,{%1,%2};" : "=l"(r) : "f"(a), "f"(b)); return r;
}
__device__ __forceinline__ u64 f2fma(u64 a, u64 b, u64 c) {
    u64 d; asm("fma.rn.f32x2 %0,%1,%2,%3;" : "=l"(d) : "l"(a), "l"(b), "l"(c)); return d;
}
__device__ __forceinline__ void f2unpack(u64 v, float& a, float& b) {
    asm("mov.b64 {%0,%1},%2;" : "=f"(a), "=f"(b) : "l"(v));
}
__device__ __forceinline__ void red2(float* p, float a, float b) {
    asm volatile("red.global.add.v2.f32 [%0],{%1,%2};" :: "l"(p), "f"(a), "f"(b) : "memory");
}
__device__ __forceinline__ float hadd_u64(u64 v) {
    float a, b; f2unpack(v, a, b); return a + b;
}
template<int N> __device__ __forceinline__ void cpwait() {
    asm volatile("cp.async.wait_group %0;" :: "n"(N) : "memory");
}
__device__ __forceinline__ void cpcommit() {
    asm volatile("cp.async.commit_group;" ::: "memory");
}

// ---------------- setup kernels ----------------
__global__ void k_zero(float* __restrict__ out) {
    int i = blockIdx.x * blockDim.x + threadIdx.x;
    int stride = gridDim.x * blockDim.x;
    int4* p = (int4*)g_cnt;
    const int n4 = (NN * RR) / 4;
    for (int j = i; j < n4; j += stride) p[j] = make_int4(0, 0, 0, 0);
    float4 z4 = make_float4(0.f, 0.f, 0.f, 0.f);
    float4* h0 = (float4*)g_h0;
    float4* h1 = (float4*)g_h1;
    float4* o4 = (float4*)out;
    const int m4 = (NN * HD) / 4;
    for (int j = i; j < m4; j += stride) { h0[j] = z4; h1[j] = z4; o4[j] = z4; }
    if (i < RR) g_hist[i] = 0;
    if (i == RR) g_done = 0;
}

__global__ void __launch_bounds__(512) k_count(const int* __restrict__ dst,
                                               const int* __restrict__ et) {
    __shared__ int sh[RR];
    __shared__ bool last;
    for (int i = threadIdx.x; i < RR; i += blockDim.x) sh[i] = 0;
    __syncthreads();
    const int4* d4 = (const int4*)dst;
    const int4* r4 = (const int4*)et;
    int i = blockIdx.x * blockDim.x + threadIdx.x;
    int stride = gridDim.x * blockDim.x;
    for (; i < EE / 4; i += stride) {
        int4 d = __ldg(d4 + i);
        int4 r = __ldg(r4 + i);
        atomicAdd(&g_cnt[d.x * RR + r.x], 1);
        atomicAdd(&g_cnt[d.y * RR + r.y], 1);
        atomicAdd(&g_cnt[d.z * RR + r.z], 1);
        atomicAdd(&g_cnt[d.w * RR + r.w], 1);
        atomicAdd(&sh[r.x], 1);
        atomicAdd(&sh[r.y], 1);
        atomicAdd(&sh[r.z], 1);
        atomicAdd(&sh[r.w], 1);
    }
    __syncthreads();
    for (int j = threadIdx.x; j < RR; j += blockDim.x) atomicAdd(&g_hist[j], sh[j]);
    if (threadIdx.x == 0) {
        __threadfence();
        int t = atomicAdd(&g_done, 1);
        last = (t == (int)gridDim.x - 1);
    }
    __syncthreads();
    if (last && threadIdx.x == 0) {
        __threadfence();
        int off = 0;
        for (int r = 0; r < RR; r++) { g_cursor[r] = off; off += g_hist[r]; }
    }
}

__global__ void __launch_bounds__(512) k_scatter(const int* __restrict__ src,
                                                 const int* __restrict__ dst,
                                                 const int* __restrict__ et) {
    __shared__ int shh[RR];
    __shared__ int shb[RR];
    int base = blockIdx.x * SC_CH;
    int end = base + SC_CH; if (end > EE) end = EE;

    for (int i = threadIdx.x; i < RR; i += blockDim.x) shh[i] = 0;
    __syncthreads();
    for (int e = base + threadIdx.x; e < end; e += blockDim.x)
        atomicAdd(&shh[__ldg(et + e)], 1);
    __syncthreads();
    for (int r = threadIdx.x; r < RR; r += blockDim.x) {
        shb[r] = atomicAdd(&g_cursor[r], shh[r]);
        shh[r] = 0;
    }
    __syncthreads();
    for (int e = base + threadIdx.x; e < end; e += blockDim.x) {
        int r = __ldg(et + e);
        int p = shb[r] + atomicAdd(&shh[r], 1);
        int d = __ldg(dst + e);
        int c = __ldg(&g_cnt[d * RR + r]);
        float sc = 1.0f / (float)(c > 1 ? c : 1);
        g_ep[p] = make_int4(__ldg(src + e), d, r, __float_as_int(sc));
    }
}

// ============ edge transform + scatter, block-diagonal W [R,4,16,16] ============
// cp.async double-buffered gather pipeline: 4-edge batches, per-warp smem stages.
__device__ __forceinline__ void bd_prefetch(const float* __restrict__ x, int base, int e1,
                                            int4* ep, float* stg, int lane) {
#pragma unroll
    for (int j = 0; j < EB; j++) {
        if (base + j < e1) {
            ep[j] = __ldg(&g_ep[base + j]);
            uint32_t s = (uint32_t)__cvta_generic_to_shared(stg + j * 64 + lane * 2);
            const float* g = x + (size_t)ep[j].x * 64 + lane * 2;
            asm volatile("cp.async.ca.shared.global [%0], [%1], 8;" :: "r"(s), "l"(g));
        }
    }
    cpcommit();
}

__device__ __forceinline__ void bd_compute(const int4* ep, const float* stg, int base, int e1,
                                           const float* __restrict__ wrel, int b, int cb,
                                           u64* w0, u64* w1, int& prev,
                                           float* __restrict__ out, int lane) {
#pragma unroll
    for (int j = 0; j < EB; j++) {
        if (base + j < e1) {
            int4 e = ep[j];
            if (e.z != prev) {
                prev = e.z;
                const float* wb = wrel + ((size_t)e.z * NB + b) * 256;
#pragma unroll
                for (int t = 0; t < 8; t++) {
                    w0[t] = f2pack(__ldg(wb + (2 * t) * 16 + cb),
                                   __ldg(wb + (2 * t + 1) * 16 + cb));
                    w1[t] = f2pack(__ldg(wb + (2 * t) * 16 + cb + 1),
                                   __ldg(wb + (2 * t + 1) * 16 + cb + 1));
                }
            }
            const ulonglong2* xr = (const ulonglong2*)(stg + j * 64 + b * 16);
            ulonglong2 p0 = xr[0], p1 = xr[1], p2 = xr[2], p3 = xr[3];
            u64 a0 = 0ull, a1 = 0ull;
            a0 = f2fma(p0.x, w0[0], a0);  a1 = f2fma(p0.x, w1[0], a1);
            a0 = f2fma(p0.y, w0[1], a0);  a1 = f2fma(p0.y, w1[1], a1);
            a0 = f2fma(p1.x, w0[2], a0);  a1 = f2fma(p1.x, w1[2], a1);
            a0 = f2fma(p1.y, w0[3], a0);  a1 = f2fma(p1.y, w1[3], a1);
            a0 = f2fma(p2.x, w0[4], a0);  a1 = f2fma(p2.x, w1[4], a1);
            a0 = f2fma(p2.y, w0[5], a0);  a1 = f2fma(p2.y, w1[5], a1);
            a0 = f2fma(p3.x, w0[6], a0);  a1 = f2fma(p3.x, w1[6], a1);
            a0 = f2fma(p3.y, w0[7], a0);  a1 = f2fma(p3.y, w1[7], a1);
            float sc = __int_as_float(e.w);
            red2(out + (size_t)e.y * 64 + 2 * lane, hadd_u64(a0) * sc, hadd_u64(a1) * sc);
        }
    }
}

__global__ void __launch_bounds__(128) k_edge_bd(const float* __restrict__ xio, int wx,
                                                 const float* __restrict__ wrel,
                                                 float* __restrict__ oio, int wo, int chunk) {
    __shared__ __align__(16) float sx[4][2][EB][64];
    const float* x = pick_cbuf(wx, xio);
    float* out = pick_buf(wo, oio);
    int wid = threadIdx.x >> 5, lane = threadIdx.x & 31;
    int gw = blockIdx.x * 4 + wid;
    long e0l = (long)gw * chunk;
    if (e0l >= EE) return;
    int e0 = (int)e0l, e1 = e0 + chunk; if (e1 > EE) e1 = EE;

    int b  = lane >> 3;
    int cb = 2 * (lane & 7);
    u64 w0[8], w1[8];
    int prev = -1;
    float* st0 = &sx[wid][0][0][0];
    float* st1 = &sx[wid][1][0][0];

    int nbt = (e1 - e0 + EB - 1) / EB;
    int4 epA[EB], epB[EB];
    bd_prefetch(x, e0, e1, epA, st0, lane);

    for (int bt = 0; bt < nbt; bt += 2) {
        int baseA = e0 + bt * EB;
        if (bt + 1 < nbt) { bd_prefetch(x, baseA + EB, e1, epB, st1, lane); cpwait<1>(); }
        else cpwait<0>();
        __syncwarp();
        bd_compute(epA, st0, baseA, e1, wrel, b, cb, w0, w1, prev, out, lane);
        __syncwarp();
        if (bt + 1 >= nbt) break;
        int baseB = baseA + EB;
        if (bt + 2 < nbt) { bd_prefetch(x, baseB + EB, e1, epA, st0, lane); cpwait<1>(); }
        else cpwait<0>();
        __syncwarp();
        bd_compute(epB, st1, baseB, e1, wrel, b, cb, w0, w1, prev, out, lane);
        __syncwarp();
    }
}

// ============ edge transform + scatter, full W [R,64,64], d-split warp pairs ============
__device__ __forceinline__ void fu_prefetch(const float* __restrict__ x, int base, int e1,
                                            int4* ep, float* stg, int lane, int d0) {
#pragma unroll
    for (int j = 0; j < EB; j++) {
        if (base + j < e1) {
            ep[j] = __ldg(&g_ep[base + j]);
            uint32_t s = (uint32_t)__cvta_generic_to_shared(stg + j * 32 + lane);
            const float* g = x + (size_t)ep[j].x * 64 + d0 + lane;
            asm volatile("cp.async.ca.shared.global [%0], [%1], 4;" :: "r"(s), "l"(g));
        }
    }
    cpcommit();
}

__device__ __forceinline__ void fu_compute(const int4* ep, const float* stg, int base, int e1,
                                           const float* __restrict__ wrel, int c0, int d0,
                                           u64* w0, u64* w1, int& prev,
                                           float* __restrict__ out) {
#pragma unroll
    for (int j = 0; j < EB; j++) {
        if (base + j < e1) {
            int4 e = ep[j];
            if (e.z != prev) {
                prev = e.z;
                const float* wb = wrel + (size_t)e.z * 4096 + (size_t)d0 * 64;
#pragma unroll
                for (int t = 0; t < 16; t++) {
                    w0[t] = f2pack(__ldg(wb + (2 * t) * 64 + c0),
                                   __ldg(wb + (2 * t + 1) * 64 + c0));
                    w1[t] = f2pack(__ldg(wb + (2 * t) * 64 + c0 + 1),
                                   __ldg(wb + (2 * t + 1) * 64 + c0 + 1));
                }
            }
            const ulonglong2* xr = (const ulonglong2*)(stg + j * 32);
            u64 a0 = 0ull, b0a = 0ull, a1 = 0ull, b1a = 0ull;
#pragma unroll
            for (int q = 0; q < 4; q++) {
                ulonglong2 pA = xr[2 * q], pB = xr[2 * q + 1];
                int t = 4 * q;
                a0  = f2fma(pA.x, w0[t + 0], a0);
                a1  = f2fma(pA.x, w1[t + 0], a1);
                b0a = f2fma(pA.y, w0[t + 1], b0a);
                b1a = f2fma(pA.y, w1[t + 1], b1a);
                a0  = f2fma(pB.x, w0[t + 2], a0);
                a1  = f2fma(pB.x, w1[t + 2], a1);
                b0a = f2fma(pB.y, w0[t + 3], b0a);
                b1a = f2fma(pB.y, w1[t + 3], b1a);
            }
            float sc = __int_as_float(e.w);
            float r0 = (hadd_u64(a0) + hadd_u64(b0a)) * sc;
            float r1 = (hadd_u64(a1) + hadd_u64(b1a)) * sc;
            red2(out + (size_t)e.y * 64 + c0, r0, r1);
        }
    }
}

__global__ void __launch_bounds__(128) k_edge_full(const float* __restrict__ xio, int wx,
                                                   const float* __restrict__ wrel,
                                                   float* __restrict__ oio, int wo, int chunk) {
    __shared__ __align__(16) float sx[4][2][EB][32];
    const float* x = pick_cbuf(wx, xio);
    float* out = pick_buf(wo, oio);
    int wid = threadIdx.x >> 5, lane = threadIdx.x & 31;
    int gw = blockIdx.x * 4 + wid;
    int pair = gw >> 1, dh = gw & 1;
    long e0l = (long)pair * chunk;
    if (e0l >= EE) return;
    int e0 = (int)e0l, e1 = e0 + chunk; if (e1 > EE) e1 = EE;

    int c0 = 2 * lane;
    int d0 = 32 * dh;
    u64 w0[16], w1[16];
    int prev = -1;
    float* st0 = &sx[wid][0][0][0];
    float* st1 = &sx[wid][1][0][0];

    int nbt = (e1 - e0 + EB - 1) / EB;
    int4 epA[EB], epB[EB];
    fu_prefetch(x, e0, e1, epA, st0, lane, d0);

    for (int bt = 0; bt < nbt; bt += 2) {
        int baseA = e0 + bt * EB;
        if (bt + 1 < nbt) { fu_prefetch(x, baseA + EB, e1, epB, st1, lane, d0); cpwait<1>(); }
        else cpwait<0>();
        __syncwarp();
        fu_compute(epA, st0, baseA, e1, wrel, c0, d0, w0, w1, prev, out);
        __syncwarp();
        if (bt + 1 >= nbt) break;
        int baseB = baseA + EB;
        if (bt + 2 < nbt) { fu_prefetch(x, baseB + EB, e1, epA, st0, lane, d0); cpwait<1>(); }
        else cpwait<0>();
        __syncwarp();
        fu_compute(epB, st1, baseB, e1, wrel, c0, d0, w0, w1, prev, out);
        __syncwarp();
    }
}

// ============ fused root GEMV + add-edge-sums + (optional) ReLU, column-split ============
// Warp pair: warp dh owns cols [32*dh, 32*dh+32); lane owns col c = 32*dh+lane over all d.
// out[n,c] = act( edge_sum[n,c] + sum_d x[n,d]*W[d,c] + bias[c] ) — unique owner, no atomics.
// FIXED indexing: xr[k] = floats 4k..4k+3 = d-pairs (2k, 2k+1) -> wc[2k], wc[2k+1].
__global__ void __launch_bounds__(128) k_root_fused(const float* __restrict__ xio, int wx,
                                                    const float* __restrict__ w,
                                                    const float* __restrict__ bias,
                                                    float* __restrict__ oio, int wo,
                                                    int dorelu) {
    const float* x = pick_cbuf(wx, xio);
    float* out = pick_buf(wo, oio);
    int gw = (blockIdx.x * blockDim.x + threadIdx.x) >> 5;
    int lane = threadIdx.x & 31;
    int pair = gw >> 1, dh = gw & 1;
    int npairs = (gridDim.x * blockDim.x) >> 6;
    int c = 32 * dh + lane;

    u64 wc[32];   // wc[t] = {W[2t][c], W[2t+1][c]}
#pragma unroll
    for (int t = 0; t < 32; t++)
        wc[t] = f2pack(__ldg(w + (2 * t) * 64 + c), __ldg(w + (2 * t + 1) * 64 + c));
    float bc = __ldg(bias + c);

    for (int n = pair; n < NN; n += npairs) {
        const ulonglong2* xr = (const ulonglong2*)(x + (size_t)n * 64);
        u64 a0 = 0ull, a1 = 0ull, a2 = 0ull, a3 = 0ull;
#pragma unroll
        for (int k = 0; k < 16; k += 2) {
            ulonglong2 pA = xr[k], pB = xr[k + 1];
            a0 = f2fma(pA.x, wc[2 * k + 0], a0);
            a1 = f2fma(pA.y, wc[2 * k + 1], a1);
            a2 = f2fma(pB.x, wc[2 * k + 2], a2);
            a3 = f2fma(pB.y, wc[2 * k + 3], a3);
        }
        float* op = out + (size_t)n * 64 + c;
        float v = *op + hadd_u64(a0) + hadd_u64(a1) + hadd_u64(a2) + hadd_u64(a3) + bc;
        if (dorelu) v = fmaxf(v, 0.f);
        *op = v;
    }
}

// ---------------- host ----------------
extern "C" void kernel_launch(void* const* d_in, const int* in_sizes, int n_in,
                              void* d_out, int out_size) {
    const float* x       = (const float*)d_in[0];
    const int*   eidx    = (const int*)d_in[1];
    const int*   src     = eidx;
    const int*   dst     = eidx + EE;
    const int*   et      = (const int*)d_in[2];
    const float* w0_rel  = (const float*)d_in[3];
    const float* w0_root = (const float*)d_in[4];
    const float* b0      = (const float*)d_in[5];
    const float* w1_rel  = (const float*)d_in[6];
    const float* w1_root = (const float*)d_in[7];
    const float* b1      = (const float*)d_in[8];
    const float* w2_rel  = (const float*)d_in[9];
    const float* w2_root = (const float*)d_in[10];
    const float* b2      = (const float*)d_in[11];
    float* out = (float*)d_out;

    k_zero<<<1280, 512>>>(out);
    k_count<<<400, 512>>>(dst, et);
    const int SC_BLOCKS = (EE + SC_CH - 1) / SC_CH;     // 391
    k_scatter<<<SC_BLOCKS, 512>>>(src, dst, et);

    const int EBLOCKS = 2368;
    const int TW = EBLOCKS * 4;
    const int chunk = (EE + TW - 1) / TW;               // ~85 edges/warp

    const int FPAIRS = EBLOCKS * 2;                     // 4736 pairs
    const int chunkF = (EE + FPAIRS - 1) / FPAIRS;      // ~169 edges/pair

    // layer 0: edges into zeroed h0, then fused root+relu
    k_edge_bd   <<<EBLOCKS, 128>>>(x, 2, w0_rel, nullptr, 0, chunk);  // launch #4 -> profiled
    k_root_fused<<<1024, 128>>>(x, 2, w0_root, b0, nullptr, 0, 1);
    // layer 1
    k_edge_bd   <<<EBLOCKS, 128>>>(nullptr, 0, w1_rel, nullptr, 1, chunk);
    k_root_fused<<<1024, 128>>>(nullptr, 0, w1_root, b1, nullptr, 1, 1);
    // layer 2 (no relu)
    k_edge_full <<<EBLOCKS, 128>>>(nullptr, 1, w2_rel, out, 2, chunkF);
    k_root_fused<<<1024, 128>>>(nullptr, 1, w2_root, b2, out, 2, 0);
}